// round 11
// baseline (speedup 1.0000x reference)
#include <cuda_runtime.h>
#include <math.h>

#define NB 64
#define NT 2048
#define ND 64
#define NTM 2047
#define NG 4
#define NGD 16

// ---------------- device scratch (no allocations allowed) ----------------
__device__ float g_S[NG * NGD * 64];                    // skew matrices, 16 KB
__device__ float g_fp[(size_t)NB * NTM * 64];           // projected features, 33.5 MB
__device__ float g_h[(size_t)NB * NT * ND];             // h = x + interp(f), 33.5 MB
__device__ float g_part[16 * NB * ND];                  // pooled partial sums (deterministic)
__device__ float g_sgate[NB * ND];                      // SE gate

// ---------------- K1: build S = tril(W,-1) - tril(W,-1)^T ----------------
__global__ void k_prep(const float* __restrict__ W) {
    int i = blockIdx.x * blockDim.x + threadIdx.x;
    if (i < NG * NGD * 64) {
        int j = i & 7;
        int r = (i >> 3) & 7;
        int gd = i >> 6;
        float v = 0.f;
        if (r > j)      v =  W[gd * 64 + r * 8 + j];
        else if (r < j) v = -W[gd * 64 + j * 8 + r];
        g_S[i] = v;
    }
}

__device__ __forceinline__ void fma8(float* acc, float s, float4 r0, float4 r1) {
    acc[0] = fmaf(s, r0.x, acc[0]);
    acc[1] = fmaf(s, r0.y, acc[1]);
    acc[2] = fmaf(s, r0.z, acc[2]);
    acc[3] = fmaf(s, r0.w, acc[3]);
    acc[4] = fmaf(s, r1.x, acc[4]);
    acc[5] = fmaf(s, r1.y, acc[5]);
    acc[6] = fmaf(s, r1.z, acc[6]);
    acc[7] = fmaf(s, r1.w, acc[7]);
}

// ---------------- K2: expm + LN + projection, fused --------------------
// 8 threads per 8x8 matrix (one row each). One warp = one (b,t): lanes
// [8g, 8g+8) handle group g. Projection partials reduced across groups
// with shfl_xor(8)/shfl_xor(16).
__global__ void __launch_bounds__(256) k_main(
    const float* __restrict__ x, const float* __restrict__ mask,
    const float* __restrict__ lng, const float* __restrict__ lnb,
    const float* __restrict__ pw, const float* __restrict__ pb) {
    // 32 matrix slots, stride 68 floats -> bank offset 4*slot, conflict-free
    __shared__ float As[32 * 68];

    const int lane = threadIdx.x & 31;
    const int warp = threadIdx.x >> 5;
    const int g = lane >> 3;
    const int r = lane & 7;
    float* Asl = As + (warp * 4 + g) * 68;

    const int bt = blockIdx.x * 8 + warp;          // (b,t) pair, t in [0, 2046]
    const int b = bt / NTM;
    const int t = bt - b * NTM;
    const float mk = mask[b * NT + t + 1];

    const float* xp = x + (size_t)(b * NT + t) * ND + g * NGD;
    float4 a0 = *(const float4*)(xp + 0);
    float4 a1 = *(const float4*)(xp + 4);
    float4 a2 = *(const float4*)(xp + 8);
    float4 a3 = *(const float4*)(xp + 12);
    float4 c0 = *(const float4*)(xp + ND + 0);
    float4 c1 = *(const float4*)(xp + ND + 4);
    float4 c2 = *(const float4*)(xp + ND + 8);
    float4 c3 = *(const float4*)(xp + ND + 12);

    float dx[16];
    dx[0]  = (c0.x - a0.x) * mk;  dx[1]  = (c0.y - a0.y) * mk;
    dx[2]  = (c0.z - a0.z) * mk;  dx[3]  = (c0.w - a0.w) * mk;
    dx[4]  = (c1.x - a1.x) * mk;  dx[5]  = (c1.y - a1.y) * mk;
    dx[6]  = (c1.z - a1.z) * mk;  dx[7]  = (c1.w - a1.w) * mk;
    dx[8]  = (c2.x - a2.x) * mk;  dx[9]  = (c2.y - a2.y) * mk;
    dx[10] = (c2.z - a2.z) * mk;  dx[11] = (c2.w - a2.w) * mk;
    dx[12] = (c3.x - a3.x) * mk;  dx[13] = (c3.y - a3.y) * mk;
    dx[14] = (c3.z - a3.z) * mk;  dx[15] = (c3.w - a3.w) * mk;

    // M row r = sum_d dx[d] * S[g,d,r,:], then scale by 2^-6
    float a[8];
#pragma unroll
    for (int j = 0; j < 8; j++) a[j] = 0.f;
    const float* Sp = g_S + g * (NGD * 64) + r * 8;
#pragma unroll
    for (int d = 0; d < 16; d++) {
        float4 s0 = *(const float4*)(Sp + d * 64);
        float4 s1 = *(const float4*)(Sp + d * 64 + 4);
        fma8(a, dx[d], s0, s1);
    }
#pragma unroll
    for (int j = 0; j < 8; j++) a[j] *= (1.f / 64.f);

    *(float4*)(Asl + r * 8)     = make_float4(a[0], a[1], a[2], a[3]);
    *(float4*)(Asl + r * 8 + 4) = make_float4(a[4], a[5], a[6], a[7]);
    __syncwarp();

    // Taylor-6 of exp(A)  (truncation err ~2e-9, ref uses 12)
    float term[8], out[8];
#pragma unroll
    for (int j = 0; j < 8; j++) { float v = (j == r) ? 1.f : 0.f; term[j] = v; out[j] = v; }
#pragma unroll
    for (int k = 1; k <= 6; k++) {
        float acc[8];
#pragma unroll
        for (int j = 0; j < 8; j++) acc[j] = 0.f;
#pragma unroll
        for (int kk = 0; kk < 8; kk++) {
            float4 r0 = *(const float4*)(Asl + kk * 8);
            float4 r1 = *(const float4*)(Asl + kk * 8 + 4);
            fma8(acc, term[kk], r0, r1);
        }
        const float invk = 1.f / (float)k;
#pragma unroll
        for (int j = 0; j < 8; j++) { term[j] = acc[j] * invk; out[j] += term[j]; }
    }

    // 6 squarings: out = out @ out
#pragma unroll 1
    for (int sq = 0; sq < 6; sq++) {
        __syncwarp();
        *(float4*)(Asl + r * 8)     = make_float4(out[0], out[1], out[2], out[3]);
        *(float4*)(Asl + r * 8 + 4) = make_float4(out[4], out[5], out[6], out[7]);
        __syncwarp();
        float acc[8];
#pragma unroll
        for (int j = 0; j < 8; j++) acc[j] = 0.f;
#pragma unroll
        for (int kk = 0; kk < 8; kk++) {
            float4 r0 = *(const float4*)(Asl + kk * 8);
            float4 r1 = *(const float4*)(Asl + kk * 8 + 4);
            fma8(acc, out[kk], r0, r1);
        }
#pragma unroll
        for (int j = 0; j < 8; j++) out[j] = acc[j];
    }

    // LayerNorm over the 64 matrix entries (reduce across the 8-lane group)
    float sum = 0.f, sqs = 0.f;
#pragma unroll
    for (int j = 0; j < 8; j++) { sum += out[j]; sqs = fmaf(out[j], out[j], sqs); }
#pragma unroll
    for (int off = 1; off < 8; off <<= 1) {
        sum += __shfl_xor_sync(0xffffffffu, sum, off);
        sqs += __shfl_xor_sync(0xffffffffu, sqs, off);
    }
    float mean = sum * (1.f / 64.f);
    float var  = sqs * (1.f / 64.f) - mean * mean;
    float rstd = rsqrtf(var + 1e-5f);

    float4 lg0 = *(const float4*)(lng + r * 8);
    float4 lg1 = *(const float4*)(lng + r * 8 + 4);
    float4 lb0 = *(const float4*)(lnb + r * 8);
    float4 lb1 = *(const float4*)(lnb + r * 8 + 4);
    float fn[8];
    fn[0] = (out[0] - mean) * rstd * lg0.x + lb0.x;
    fn[1] = (out[1] - mean) * rstd * lg0.y + lb0.y;
    fn[2] = (out[2] - mean) * rstd * lg0.z + lb0.z;
    fn[3] = (out[3] - mean) * rstd * lg0.w + lb0.w;
    fn[4] = (out[4] - mean) * rstd * lg1.x + lb1.x;
    fn[5] = (out[5] - mean) * rstd * lg1.y + lb1.y;
    fn[6] = (out[6] - mean) * rstd * lg1.z + lb1.z;
    fn[7] = (out[7] - mean) * rstd * lg1.w + lb1.w;

    // stage normalized features, then fused projection f(256) @ P(256,64)
    __syncwarp();
    *(float4*)(Asl + r * 8)     = make_float4(fn[0], fn[1], fn[2], fn[3]);
    *(float4*)(Asl + r * 8 + 4) = make_float4(fn[4], fn[5], fn[6], fn[7]);
    __syncwarp();

    float acc[8];
#pragma unroll
    for (int j = 0; j < 8; j++) acc[j] = 0.f;
    const float* pwp = pw + (g * 64) * 64 + r * 8;   // row (g*64+c), cols [r*8, r*8+8)
#pragma unroll 4
    for (int c = 0; c < 64; c++) {
        float fv = Asl[c];                            // group broadcast
        float4 p0 = *(const float4*)(pwp + c * 64);
        float4 p1 = *(const float4*)(pwp + c * 64 + 4);
        fma8(acc, fv, p0, p1);
    }
    // sum partials over the 4 groups
#pragma unroll
    for (int j = 0; j < 8; j++) {
        acc[j] += __shfl_xor_sync(0xffffffffu, acc[j], 8);
        acc[j] += __shfl_xor_sync(0xffffffffu, acc[j], 16);
    }
    if (g == 0) {
        float4 pb0 = *(const float4*)(pb + r * 8);
        float4 pb1 = *(const float4*)(pb + r * 8 + 4);
        float* op = g_fp + (size_t)bt * 64 + r * 8;
        *(float4*)(op)     = make_float4(acc[0] + pb0.x, acc[1] + pb0.y, acc[2] + pb0.z, acc[3] + pb0.w);
        *(float4*)(op + 4) = make_float4(acc[4] + pb1.x, acc[5] + pb1.y, acc[6] + pb1.z, acc[7] + pb1.w);
    }
}

// ---------------- K3: h = x + lin_interp(f), masked pooled partials -----
__global__ void __launch_bounds__(256) k_interp(
    const float* __restrict__ x, const float* __restrict__ mask) {
    const int b  = blockIdx.y;
    const int d  = threadIdx.x & 63;
    const int tq = threadIdx.x >> 6;
    const float sc = (float)(2047.0 / 2048.0);
    float acc = 0.f;
    const int t0 = blockIdx.x * 128;
#pragma unroll 4
    for (int i = 0; i < 32; i++) {
        int t = t0 + i * 4 + tq;
        float pos = ((float)t + 0.5f) * sc - 0.5f;
        pos = fminf(fmaxf(pos, 0.f), 2046.0f);
        float fl = floorf(pos);
        int i0 = (int)fl;
        int i1 = min(i0 + 1, 2046);
        float w = pos - fl;
        float f0 = g_fp[((size_t)b * NTM + i0) * 64 + d];
        float f1 = g_fp[((size_t)b * NTM + i1) * 64 + d];
        size_t xi = ((size_t)b * NT + t) * 64 + d;
        float hv = x[xi] + f0 * (1.f - w) + f1 * w;
        g_h[xi] = hv;
        acc += hv * mask[b * NT + t];
    }
    __shared__ float red[256];
    red[threadIdx.x] = acc;
    __syncthreads();
    if (tq == 0) {
        float s = red[d] + red[d + 64] + red[d + 128] + red[d + 192];
        g_part[blockIdx.x * (NB * ND) + b * ND + d] = s;   // deterministic partials
    }
}

// ---------------- K4: SE gate (tiny) + copy mask into output tail -------
__global__ void k_se(const float* __restrict__ mask,
                     const float* __restrict__ w1, const float* __restrict__ b1,
                     const float* __restrict__ w2, const float* __restrict__ b2,
                     float* __restrict__ outp, long long out_size) {
    const int b = blockIdx.x;        // 64 blocks x 64 threads
    const int tid = threadIdx.x;
    __shared__ float sm[64];
    __shared__ float hid[4];
    __shared__ float dsh;

    float ds = 0.f;
    for (int t = tid; t < NT; t += 64) ds += mask[b * NT + t];
    sm[tid] = ds;
    __syncthreads();
    if (tid == 0) {
        float s = 0.f;
        for (int i = 0; i < 64; i++) s += sm[i];
        dsh = s;
    }
    __syncthreads();
    const float denom = dsh;

    float p = 0.f;
#pragma unroll
    for (int c = 0; c < 16; c++) p += g_part[c * (NB * ND) + b * ND + tid];
    p /= denom;
    __syncthreads();
    sm[tid] = p;
    __syncthreads();
    if (tid < 4) {
        float acc = b1[tid];
        for (int dd = 0; dd < 64; dd++) acc += sm[dd] * w1[dd * 4 + tid];
        hid[tid] = 0.5f * acc * (1.f + erff(acc * 0.70710678118654752f)); // exact GELU
    }
    __syncthreads();
    float o = b2[tid];
#pragma unroll
    for (int j = 0; j < 4; j++) o += hid[j] * w2[j * 64 + tid];
    g_sgate[b * ND + tid] = 1.f / (1.f + expf(-o));

    // mask passthrough (second tuple element), if the output buffer holds it
    const size_t base = (size_t)NB * NT * ND;
    for (int t = tid; t < NT; t += 64) {
        size_t idx = base + (size_t)b * NT + t;
        if ((long long)idx < out_size) outp[idx] = mask[b * NT + t];
    }
}

// ---------------- K5: out = h * s + x ------------------------------------
__global__ void __launch_bounds__(256) k_final(
    const float* __restrict__ x, float* __restrict__ out) {
    const int i = blockIdx.x * 256 + threadIdx.x;    // < NB*NT*ND = 2^23
    const int d = i & 63;
    const int b = i >> 17;                           // NT*ND = 2^17
    const float s = g_sgate[b * ND + d];
    out[i] = g_h[i] * s + x[i];
}

// ---------------- launch ---------------------------------------------------
extern "C" void kernel_launch(void* const* d_in, const int* in_sizes, int n_in,
                              void* d_out, int out_size) {
    const float* x     = (const float*)d_in[0];
    const float* mask  = (const float*)d_in[1];
    const float* W     = (const float*)d_in[2];
    const float* lng   = (const float*)d_in[3];
    const float* lnb   = (const float*)d_in[4];
    const float* pw    = (const float*)d_in[5];
    const float* pb    = (const float*)d_in[6];
    const float* w1    = (const float*)d_in[7];
    const float* b1    = (const float*)d_in[8];
    const float* w2    = (const float*)d_in[9];
    const float* b2    = (const float*)d_in[10];
    float* out = (float*)d_out;

    k_prep<<<16, 256>>>(W);
    k_main<<<(NB * NTM) / 8, 256>>>(x, mask, lng, lnb, pw, pb);   // 16376 blocks
    dim3 gi(16, NB);
    k_interp<<<gi, 256>>>(x, mask);
    k_se<<<NB, 64>>>(mask, w1, b1, w2, b2, out, (long long)out_size);
    k_final<<<(NB * NT * ND) / 256, 256>>>(x, out);               // 32768 blocks
}

// round 12
// speedup vs baseline: 1.0000x; 1.0000x over previous
#include <cuda_runtime.h>
#include <math.h>

#define NB 64
#define NT 2048
#define ND 64
#define NTM 2047
#define NG 4
#define NGD 16

// ---------------- device scratch (no allocations allowed) ----------------
__device__ float g_S[NG * NGD * 64];                    // skew matrices, 16 KB
__device__ float g_fp[(size_t)NB * NTM * 64];           // projected features, 33.5 MB
__device__ float g_h[(size_t)NB * NT * ND];             // h = x + interp(f), 33.5 MB
__device__ float g_part[16 * NB * ND];                  // pooled partial sums (deterministic)
__device__ float g_sgate[NB * ND];                      // SE gate

// ---------------- K1: build S = tril(W,-1) - tril(W,-1)^T ----------------
__global__ void k_prep(const float* __restrict__ W) {
    int i = blockIdx.x * blockDim.x + threadIdx.x;
    if (i < NG * NGD * 64) {
        int j = i & 7;
        int r = (i >> 3) & 7;
        int gd = i >> 6;
        float v = 0.f;
        if (r > j)      v =  W[gd * 64 + r * 8 + j];
        else if (r < j) v = -W[gd * 64 + j * 8 + r];
        g_S[i] = v;
    }
}

__device__ __forceinline__ void fma8(float* acc, float s, float4 r0, float4 r1) {
    acc[0] = fmaf(s, r0.x, acc[0]);
    acc[1] = fmaf(s, r0.y, acc[1]);
    acc[2] = fmaf(s, r0.z, acc[2]);
    acc[3] = fmaf(s, r0.w, acc[3]);
    acc[4] = fmaf(s, r1.x, acc[4]);
    acc[5] = fmaf(s, r1.y, acc[5]);
    acc[6] = fmaf(s, r1.z, acc[6]);
    acc[7] = fmaf(s, r1.w, acc[7]);
}

// ---------------- K2: expm + LN + projection, fused --------------------
// 8 threads per 8x8 matrix (one row each). One warp = one (b,t): lanes
// [8g, 8g+8) handle group g. Projection partials reduced across groups
// with shfl_xor(8)/shfl_xor(16).
__global__ void __launch_bounds__(256) k_main(
    const float* __restrict__ x, const float* __restrict__ mask,
    const float* __restrict__ lng, const float* __restrict__ lnb,
    const float* __restrict__ pw, const float* __restrict__ pb) {
    // 32 matrix slots, stride 68 floats -> bank offset 4*slot, conflict-free
    __shared__ float As[32 * 68];

    const int lane = threadIdx.x & 31;
    const int warp = threadIdx.x >> 5;
    const int g = lane >> 3;
    const int r = lane & 7;
    float* Asl = As + (warp * 4 + g) * 68;

    const int bt = blockIdx.x * 8 + warp;          // (b,t) pair, t in [0, 2046]
    const int b = bt / NTM;
    const int t = bt - b * NTM;
    const float mk = mask[b * NT + t + 1];

    const float* xp = x + (size_t)(b * NT + t) * ND + g * NGD;
    float4 a0 = *(const float4*)(xp + 0);
    float4 a1 = *(const float4*)(xp + 4);
    float4 a2 = *(const float4*)(xp + 8);
    float4 a3 = *(const float4*)(xp + 12);
    float4 c0 = *(const float4*)(xp + ND + 0);
    float4 c1 = *(const float4*)(xp + ND + 4);
    float4 c2 = *(const float4*)(xp + ND + 8);
    float4 c3 = *(const float4*)(xp + ND + 12);

    float dx[16];
    dx[0]  = (c0.x - a0.x) * mk;  dx[1]  = (c0.y - a0.y) * mk;
    dx[2]  = (c0.z - a0.z) * mk;  dx[3]  = (c0.w - a0.w) * mk;
    dx[4]  = (c1.x - a1.x) * mk;  dx[5]  = (c1.y - a1.y) * mk;
    dx[6]  = (c1.z - a1.z) * mk;  dx[7]  = (c1.w - a1.w) * mk;
    dx[8]  = (c2.x - a2.x) * mk;  dx[9]  = (c2.y - a2.y) * mk;
    dx[10] = (c2.z - a2.z) * mk;  dx[11] = (c2.w - a2.w) * mk;
    dx[12] = (c3.x - a3.x) * mk;  dx[13] = (c3.y - a3.y) * mk;
    dx[14] = (c3.z - a3.z) * mk;  dx[15] = (c3.w - a3.w) * mk;

    // M row r = sum_d dx[d] * S[g,d,r,:], then scale by 2^-6
    float a[8];
#pragma unroll
    for (int j = 0; j < 8; j++) a[j] = 0.f;
    const float* Sp = g_S + g * (NGD * 64) + r * 8;
#pragma unroll
    for (int d = 0; d < 16; d++) {
        float4 s0 = *(const float4*)(Sp + d * 64);
        float4 s1 = *(const float4*)(Sp + d * 64 + 4);
        fma8(a, dx[d], s0, s1);
    }
#pragma unroll
    for (int j = 0; j < 8; j++) a[j] *= (1.f / 64.f);

    *(float4*)(Asl + r * 8)     = make_float4(a[0], a[1], a[2], a[3]);
    *(float4*)(Asl + r * 8 + 4) = make_float4(a[4], a[5], a[6], a[7]);
    __syncwarp();

    // Taylor-6 of exp(A)  (truncation err ~2e-9, ref uses 12)
    float term[8], out[8];
#pragma unroll
    for (int j = 0; j < 8; j++) { float v = (j == r) ? 1.f : 0.f; term[j] = v; out[j] = v; }
#pragma unroll
    for (int k = 1; k <= 6; k++) {
        float acc[8];
#pragma unroll
        for (int j = 0; j < 8; j++) acc[j] = 0.f;
#pragma unroll
        for (int kk = 0; kk < 8; kk++) {
            float4 r0 = *(const float4*)(Asl + kk * 8);
            float4 r1 = *(const float4*)(Asl + kk * 8 + 4);
            fma8(acc, term[kk], r0, r1);
        }
        const float invk = 1.f / (float)k;
#pragma unroll
        for (int j = 0; j < 8; j++) { term[j] = acc[j] * invk; out[j] += term[j]; }
    }

    // 6 squarings: out = out @ out
#pragma unroll 1
    for (int sq = 0; sq < 6; sq++) {
        __syncwarp();
        *(float4*)(Asl + r * 8)     = make_float4(out[0], out[1], out[2], out[3]);
        *(float4*)(Asl + r * 8 + 4) = make_float4(out[4], out[5], out[6], out[7]);
        __syncwarp();
        float acc[8];
#pragma unroll
        for (int j = 0; j < 8; j++) acc[j] = 0.f;
#pragma unroll
        for (int kk = 0; kk < 8; kk++) {
            float4 r0 = *(const float4*)(Asl + kk * 8);
            float4 r1 = *(const float4*)(Asl + kk * 8 + 4);
            fma8(acc, out[kk], r0, r1);
        }
#pragma unroll
        for (int j = 0; j < 8; j++) out[j] = acc[j];
    }

    // LayerNorm over the 64 matrix entries (reduce across the 8-lane group)
    float sum = 0.f, sqs = 0.f;
#pragma unroll
    for (int j = 0; j < 8; j++) { sum += out[j]; sqs = fmaf(out[j], out[j], sqs); }
#pragma unroll
    for (int off = 1; off < 8; off <<= 1) {
        sum += __shfl_xor_sync(0xffffffffu, sum, off);
        sqs += __shfl_xor_sync(0xffffffffu, sqs, off);
    }
    float mean = sum * (1.f / 64.f);
    float var  = sqs * (1.f / 64.f) - mean * mean;
    float rstd = rsqrtf(var + 1e-5f);

    float4 lg0 = *(const float4*)(lng + r * 8);
    float4 lg1 = *(const float4*)(lng + r * 8 + 4);
    float4 lb0 = *(const float4*)(lnb + r * 8);
    float4 lb1 = *(const float4*)(lnb + r * 8 + 4);
    float fn[8];
    fn[0] = (out[0] - mean) * rstd * lg0.x + lb0.x;
    fn[1] = (out[1] - mean) * rstd * lg0.y + lb0.y;
    fn[2] = (out[2] - mean) * rstd * lg0.z + lb0.z;
    fn[3] = (out[3] - mean) * rstd * lg0.w + lb0.w;
    fn[4] = (out[4] - mean) * rstd * lg1.x + lb1.x;
    fn[5] = (out[5] - mean) * rstd * lg1.y + lb1.y;
    fn[6] = (out[6] - mean) * rstd * lg1.z + lb1.z;
    fn[7] = (out[7] - mean) * rstd * lg1.w + lb1.w;

    // stage normalized features, then fused projection f(256) @ P(256,64)
    __syncwarp();
    *(float4*)(Asl + r * 8)     = make_float4(fn[0], fn[1], fn[2], fn[3]);
    *(float4*)(Asl + r * 8 + 4) = make_float4(fn[4], fn[5], fn[6], fn[7]);
    __syncwarp();

    float acc[8];
#pragma unroll
    for (int j = 0; j < 8; j++) acc[j] = 0.f;
    const float* pwp = pw + (g * 64) * 64 + r * 8;   // row (g*64+c), cols [r*8, r*8+8)
#pragma unroll 4
    for (int c = 0; c < 64; c++) {
        float fv = Asl[c];                            // group broadcast
        float4 p0 = *(const float4*)(pwp + c * 64);
        float4 p1 = *(const float4*)(pwp + c * 64 + 4);
        fma8(acc, fv, p0, p1);
    }
    // sum partials over the 4 groups
#pragma unroll
    for (int j = 0; j < 8; j++) {
        acc[j] += __shfl_xor_sync(0xffffffffu, acc[j], 8);
        acc[j] += __shfl_xor_sync(0xffffffffu, acc[j], 16);
    }
    if (g == 0) {
        float4 pb0 = *(const float4*)(pb + r * 8);
        float4 pb1 = *(const float4*)(pb + r * 8 + 4);
        float* op = g_fp + (size_t)bt * 64 + r * 8;
        *(float4*)(op)     = make_float4(acc[0] + pb0.x, acc[1] + pb0.y, acc[2] + pb0.z, acc[3] + pb0.w);
        *(float4*)(op + 4) = make_float4(acc[4] + pb1.x, acc[5] + pb1.y, acc[6] + pb1.z, acc[7] + pb1.w);
    }
}

// ---------------- K3: h = x + lin_interp(f), masked pooled partials -----
__global__ void __launch_bounds__(256) k_interp(
    const float* __restrict__ x, const float* __restrict__ mask) {
    const int b  = blockIdx.y;
    const int d  = threadIdx.x & 63;
    const int tq = threadIdx.x >> 6;
    const float sc = (float)(2047.0 / 2048.0);
    float acc = 0.f;
    const int t0 = blockIdx.x * 128;
#pragma unroll 4
    for (int i = 0; i < 32; i++) {
        int t = t0 + i * 4 + tq;
        float pos = ((float)t + 0.5f) * sc - 0.5f;
        pos = fminf(fmaxf(pos, 0.f), 2046.0f);
        float fl = floorf(pos);
        int i0 = (int)fl;
        int i1 = min(i0 + 1, 2046);
        float w = pos - fl;
        float f0 = g_fp[((size_t)b * NTM + i0) * 64 + d];
        float f1 = g_fp[((size_t)b * NTM + i1) * 64 + d];
        size_t xi = ((size_t)b * NT + t) * 64 + d;
        float hv = x[xi] + f0 * (1.f - w) + f1 * w;
        g_h[xi] = hv;
        acc += hv * mask[b * NT + t];
    }
    __shared__ float red[256];
    red[threadIdx.x] = acc;
    __syncthreads();
    if (tq == 0) {
        float s = red[d] + red[d + 64] + red[d + 128] + red[d + 192];
        g_part[blockIdx.x * (NB * ND) + b * ND + d] = s;   // deterministic partials
    }
}

// ---------------- K4: SE gate (tiny) + copy mask into output tail -------
__global__ void k_se(const float* __restrict__ mask,
                     const float* __restrict__ w1, const float* __restrict__ b1,
                     const float* __restrict__ w2, const float* __restrict__ b2,
                     float* __restrict__ outp, long long out_size) {
    const int b = blockIdx.x;        // 64 blocks x 64 threads
    const int tid = threadIdx.x;
    __shared__ float sm[64];
    __shared__ float hid[4];
    __shared__ float dsh;

    float ds = 0.f;
    for (int t = tid; t < NT; t += 64) ds += mask[b * NT + t];
    sm[tid] = ds;
    __syncthreads();
    if (tid == 0) {
        float s = 0.f;
        for (int i = 0; i < 64; i++) s += sm[i];
        dsh = s;
    }
    __syncthreads();
    const float denom = dsh;

    float p = 0.f;
#pragma unroll
    for (int c = 0; c < 16; c++) p += g_part[c * (NB * ND) + b * ND + tid];
    p /= denom;
    __syncthreads();
    sm[tid] = p;
    __syncthreads();
    if (tid < 4) {
        float acc = b1[tid];
        for (int dd = 0; dd < 64; dd++) acc += sm[dd] * w1[dd * 4 + tid];
        hid[tid] = 0.5f * acc * (1.f + erff(acc * 0.70710678118654752f)); // exact GELU
    }
    __syncthreads();
    float o = b2[tid];
#pragma unroll
    for (int j = 0; j < 4; j++) o += hid[j] * w2[j * 64 + tid];
    g_sgate[b * ND + tid] = 1.f / (1.f + expf(-o));

    // mask passthrough (second tuple element), if the output buffer holds it
    const size_t base = (size_t)NB * NT * ND;
    for (int t = tid; t < NT; t += 64) {
        size_t idx = base + (size_t)b * NT + t;
        if ((long long)idx < out_size) outp[idx] = mask[b * NT + t];
    }
}

// ---------------- K5: out = h * s + x ------------------------------------
__global__ void __launch_bounds__(256) k_final(
    const float* __restrict__ x, float* __restrict__ out) {
    const int i = blockIdx.x * 256 + threadIdx.x;    // < NB*NT*ND = 2^23
    const int d = i & 63;
    const int b = i >> 17;                           // NT*ND = 2^17
    const float s = g_sgate[b * ND + d];
    out[i] = g_h[i] * s + x[i];
}

// ---------------- launch ---------------------------------------------------
extern "C" void kernel_launch(void* const* d_in, const int* in_sizes, int n_in,
                              void* d_out, int out_size) {
    const float* x     = (const float*)d_in[0];
    const float* mask  = (const float*)d_in[1];
    const float* W     = (const float*)d_in[2];
    const float* lng   = (const float*)d_in[3];
    const float* lnb   = (const float*)d_in[4];
    const float* pw    = (const float*)d_in[5];
    const float* pb    = (const float*)d_in[6];
    const float* w1    = (const float*)d_in[7];
    const float* b1    = (const float*)d_in[8];
    const float* w2    = (const float*)d_in[9];
    const float* b2    = (const float*)d_in[10];
    float* out = (float*)d_out;

    k_prep<<<16, 256>>>(W);
    k_main<<<(NB * NTM) / 8, 256>>>(x, mask, lng, lnb, pw, pb);   // 16376 blocks
    dim3 gi(16, NB);
    k_interp<<<gi, 256>>>(x, mask);
    k_se<<<NB, 64>>>(mask, w1, b1, w2, b2, out, (long long)out_size);
    k_final<<<(NB * NT * ND) / 256, 256>>>(x, out);               // 32768 blocks
}